// round 9
// baseline (speedup 1.0000x reference)
#include <cuda_runtime.h>
#include <cstdint>

#define BATCH   32
#define CIN     64
#define COUT    64
#define HH      56
#define WW      56
#define LL      3136
#define FEAT    576
#define NCHUNK  18            // 576 / 32 f per chunk
#define NTHREADS 128          // 4 warps x (32b x 16c)
#define NSTAGE  16
#define DIST    15            // prefetch distance in chunks
#define GRID    152

// ---- smem ----
// patch: [32 b][580 floats] (tf32 bits), 2320B rows (odd x16 -> ldsm conflict-free)
#define PROW_FLOATS 580
#define PROW_BYTES  2320
#define PATCH_BYTES 74240
// per-warp weight rings: 4 warps x 16 stages x [16 c][32 f] fp32 (2048 B)
#define WSTAGE_BYTES 2048
#define WRING_BYTES  (NSTAGE * WSTAGE_BYTES)     // 32768
#define RING_OFF     PATCH_BYTES
#define SMEM_TOTAL   (RING_OFF + 4 * WRING_BYTES)   // 205312

__device__ float g_xt[(size_t)BATCH * LL * CIN];

// ---------------- helpers ----------------
__device__ __forceinline__ uint32_t swz(uint32_t o) { return o ^ ((o >> 3) & 0x70); }

__device__ __forceinline__ uint32_t cvt_tf32(float v) {
    uint32_t t;
    asm("cvt.rna.tf32.f32 %0, %1;" : "=r"(t) : "f"(v));
    return t;
}
__device__ __forceinline__ uint32_t tf32r(uint32_t bits) {
    uint32_t t;
    asm("cvt.rna.tf32.f32 %0, %1;" : "=r"(t) : "f"(__uint_as_float(bits)));
    return t;
}

__device__ __forceinline__ void sts32(uint32_t a, uint32_t v) {
    asm volatile("st.shared.b32 [%0], %1;" :: "r"(a), "r"(v) : "memory");
}

__device__ __forceinline__ void cp_async16(uint32_t smem_addr, const void* gmem_ptr) {
    asm volatile("cp.async.cg.shared.global [%0], [%1], 16;\n"
                 :: "r"(smem_addr), "l"(gmem_ptr));
}

__device__ __forceinline__ void ldsm_x4(uint32_t addr, uint32_t& r0, uint32_t& r1,
                                        uint32_t& r2, uint32_t& r3) {
    asm volatile("ldmatrix.sync.aligned.m8n8.x4.shared.b16 {%0,%1,%2,%3}, [%4];"
                 : "=r"(r0), "=r"(r1), "=r"(r2), "=r"(r3) : "r"(addr));
}

__device__ __forceinline__ void mma_tf32(float* d, const uint32_t* a, const uint32_t* b) {
    asm volatile("mma.sync.aligned.m16n8k8.row.col.f32.tf32.tf32.f32 "
                 "{%0,%1,%2,%3}, {%4,%5,%6,%7}, {%8,%9}, {%0,%1,%2,%3};"
                 : "+f"(d[0]), "+f"(d[1]), "+f"(d[2]), "+f"(d[3])
                 : "r"(a[0]), "r"(a[1]), "r"(a[2]), "r"(a[3]),
                   "r"(b[0]), "r"(b[1]));
}

// ---------------- kernel 1: x NCHW -> NHWC transpose ----------------
__global__ void __launch_bounds__(256) transpose_x(const float* __restrict__ x) {
    __shared__ float tile[32][33];
    const int b  = blockIdx.z;
    const int c0 = blockIdx.y * 32;
    const int s0 = blockIdx.x * 32;
    const int tx = threadIdx.x & 31;
    const int ty = threadIdx.x >> 5;
    #pragma unroll
    for (int i = 0; i < 4; i++)
        tile[ty + 8 * i][tx] = x[((size_t)b * CIN + c0 + ty + 8 * i) * LL + s0 + tx];
    __syncthreads();
    #pragma unroll
    for (int i = 0; i < 4; i++)
        g_xt[((size_t)b * LL + s0 + ty + 8 * i) * CIN + c0 + tx] = tile[tx][ty + 8 * i];
}

// ---------------- kernel 2: persistent per-location GEMM ----------------
__global__ void __launch_bounds__(NTHREADS, 1)
lc2d_mma(const float* __restrict__ w,
         const float* __restrict__ bias,
         float* __restrict__ out)
{
    extern __shared__ char smem[];
    const uint32_t sb = (uint32_t)__cvta_generic_to_shared(smem);

    const int tid  = threadIdx.x;
    const int lane = tid & 31;
    const int warp = tid >> 5;        // 0..3, owns channels [16*warp, 16*warp+16)
    const int bx   = blockIdx.x;

    // location range: 96 CTAs get 21 locations, 56 get 20 (96*21+56*20 = 3136)
    const int cnt = 20 + (bx < 96 ? 1 : 0);
    const int l0  = bx * 20 + (bx < 96 ? bx : 96);

    // ---- weight fetch mapping ----
    const int wrow = lane >> 1;       // 0..15
    const int fsel = lane & 1;
    const float* wgf = w + ((size_t)l0 * COUT + warp * 16 + wrow) * FEAT + 4 * fsel;
    const uint32_t wsd = (uint32_t)wrow * 128 + (uint32_t)fsel * 16;   // + j*32, pre-swz
    const uint32_t ring = sb + RING_OFF + (uint32_t)warp * WRING_BYTES;

    // fetch cursor
    int kf = 0;                            // chunk index within fetch location
    int fetch_remaining = cnt * NCHUNK;

    // ---- weight prologue: 15 chunks into stages 0..14 ----
    #pragma unroll
    for (int i = 0; i < DIST; i++) {
        const uint32_t st = ring + (uint32_t)i * WSTAGE_BYTES;
        #pragma unroll
        for (int j = 0; j < 4; j++)
            cp_async16(st + swz(wsd + (uint32_t)j * 32), wgf + kf * 32 + 8 * j);
        asm volatile("cp.async.commit_group;\n");
        kf++;
        if (kf == NCHUNK) { kf = 0; wgf += (size_t)COUT * FEAT; }
    }
    fetch_remaining -= DIST;
    int stf = DIST;    // next ring stage to write

    // ---- patch prologue: stage half 0 (f 0..287, pos 0..7) of loc l0 ----
    {
        const int oh = l0 / WW, ow = l0 - (l0 / WW) * WW;
        for (int s = 0; s < 18; s++) {
            int e   = s * NTHREADS + tid;       // 0..2303
            int b   = e / 72;
            int r72 = e - b * 72;
            int rr  = r72 >> 3;
            int pos = r72 & 7;
            int ki = rr / 3, kj = rr - ki * 3;
            int h  = oh + ki - 1, wq = ow + kj - 1;
            bool ok = ((unsigned)h < HH) & ((unsigned)wq < WW);
            float4 v = make_float4(0.f, 0.f, 0.f, 0.f);
            if (ok)
                v = *(const float4*)(g_xt + ((size_t)b * LL + h * WW + wq) * CIN + pos * 4);
            uint32_t a = sb + (uint32_t)b * PROW_BYTES + (uint32_t)(36 * pos + rr) * 4;
            sts32(a,      cvt_tf32(v.x));
            sts32(a + 36, cvt_tf32(v.y));
            sts32(a + 72, cvt_tf32(v.z));
            sts32(a + 108, cvt_tf32(v.w));
        }
    }
    __syncthreads();

    // ---- fragment addressing ----
    // A = patches (m = batch): 2 m-tiles of 16 rows
    const uint32_t a_colq = (lane & 16) ? 16u : 0u;
    const uint32_t a_base0 = sb + (uint32_t)(lane & 15) * PROW_BYTES + a_colq;
    const uint32_t a_base1 = a_base0 + 16 * PROW_BYTES;
    // B = weights (n = channel): 16 rows via ldsm_x4
    const uint32_t b_off = (uint32_t)((lane & 7) + ((lane & 16) ? 8 : 0)) * 128
                         + ((lane & 8) ? 16u : 0u);     // + ks*32, pre-swz

    uint32_t stc = 0;   // consume stage

    for (int li = 0; li < cnt; li++) {
        const int l  = l0 + li;
        const int oh = l / WW, ow = l - (l / WW) * WW;
        const bool has_next = (li + 1 < cnt);
        const int l2  = has_next ? l + 1 : l;
        const int oh2 = l2 / WW, ow2 = l2 - (l2 / WW) * WW;

        float acc[2][2][4];
        #pragma unroll
        for (int mt = 0; mt < 2; mt++)
            #pragma unroll
            for (int nt = 0; nt < 2; nt++)
                #pragma unroll
                for (int q = 0; q < 4; q++) acc[mt][nt][q] = 0.0f;

        // pending staged slices (STS deferred one iteration)
        float4   pv[2];
        uint32_t pa[2];
        bool pvalid = false;

        for (int k = 0; k < NCHUNK; k++) {
            if (k == 9) __syncthreads();    // publish regions 9..17; regions 0..8 fully read

            // ---- load 2 patch slices (for half being staged) ----
            // k<9: stage half 1 (f 288..575) of CURRENT loc into regions 9..17
            // k>=9: stage half 0 of NEXT loc into regions 0..8
            const int  half     = (k < 9) ? 1 : 0;
            const int  kk       = (k < 9) ? k : k - 9;
            const bool do_stage = (k < 9) ? true : has_next;
            const int  soh = (k < 9) ? oh : oh2;
            const int  sow = (k < 9) ? ow : ow2;

            float4   nv[2];
            uint32_t na[2];
            if (do_stage) {
                #pragma unroll
                for (int u = 0; u < 2; u++) {
                    int e   = (2 * kk + u) * NTHREADS + tid;
                    int b   = e / 72;
                    int r72 = e - b * 72;
                    int rr  = r72 >> 3;
                    int pos = r72 & 7;
                    int ki = rr / 3, kj = rr - ki * 3;
                    int h  = soh + ki - 1, wq = sow + kj - 1;
                    bool ok = ((unsigned)h < HH) & ((unsigned)wq < WW);
                    nv[u] = make_float4(0.f, 0.f, 0.f, 0.f);
                    if (ok)
                        nv[u] = *(const float4*)(g_xt + ((size_t)b * LL + h * WW + wq) * CIN
                                                 + (half * 8 + pos) * 4);
                    na[u] = sb + (uint32_t)b * PROW_BYTES
                          + (uint32_t)(288 * half + 36 * pos + rr) * 4;
                }
            }

            // ---- preload A-frags for chunk k ----
            uint32_t a[2][4][4];
            #pragma unroll
            for (int ks = 0; ks < 4; ks++) {
                const uint32_t co = (uint32_t)(k * 128 + ks * 32);
                ldsm_x4(a_base0 + co, a[0][ks][0], a[0][ks][1], a[0][ks][2], a[0][ks][3]);
                ldsm_x4(a_base1 + co, a[1][ks][0], a[1][ks][1], a[1][ks][2], a[1][ks][3]);
            }

            // ---- issue next weight chunk, commit (always), wait ----
            if (fetch_remaining > 0) {
                const uint32_t st = ring + (uint32_t)stf * WSTAGE_BYTES;
                #pragma unroll
                for (int j = 0; j < 4; j++)
                    cp_async16(st + swz(wsd + (uint32_t)j * 32), wgf + kf * 32 + 8 * j);
                fetch_remaining--;
                kf++;
                if (kf == NCHUNK) { kf = 0; wgf += (size_t)COUT * FEAT; }
                stf = (stf + 1) & (NSTAGE - 1);
            }
            asm volatile("cp.async.commit_group;\n");
            asm volatile("cp.async.wait_group %0;\n" :: "n"(DIST));

            // ---- B-frags + mma ----
            const uint32_t wt = ring + stc * WSTAGE_BYTES;
            stc = (stc + 1) & (NSTAGE - 1);
            #pragma unroll
            for (int ks = 0; ks < 4; ks++) {
                uint32_t bf[4];
                ldsm_x4(wt + swz(b_off + (uint32_t)ks * 32), bf[0], bf[1], bf[2], bf[3]);
                #pragma unroll
                for (int q = 0; q < 4; q++) bf[q] = tf32r(bf[q]);
                mma_tf32(acc[0][0], a[0][ks], bf);
                mma_tf32(acc[0][1], a[0][ks], bf + 2);
                mma_tf32(acc[1][0], a[1][ks], bf);
                mma_tf32(acc[1][1], a[1][ks], bf + 2);
            }

            // ---- STS pending slices (from iteration k-1), then rotate ----
            if (pvalid) {
                #pragma unroll
                for (int u = 0; u < 2; u++) {
                    sts32(pa[u],       cvt_tf32(pv[u].x));
                    sts32(pa[u] + 36,  cvt_tf32(pv[u].y));
                    sts32(pa[u] + 72,  cvt_tf32(pv[u].z));
                    sts32(pa[u] + 108, cvt_tf32(pv[u].w));
                }
            }
            pvalid = do_stage;
            if (do_stage) {
                pv[0] = nv[0]; pv[1] = nv[1];
                pa[0] = na[0]; pa[1] = na[1];
            }
            // flush before barrier points
            if ((k == 8 || k == NCHUNK - 1) && pvalid) {
                #pragma unroll
                for (int u = 0; u < 2; u++) {
                    sts32(pa[u],       cvt_tf32(pv[u].x));
                    sts32(pa[u] + 36,  cvt_tf32(pv[u].y));
                    sts32(pa[u] + 72,  cvt_tf32(pv[u].z));
                    sts32(pa[u] + 108, cvt_tf32(pv[u].w));
                }
                pvalid = false;
            }
        }

        // ---- epilogue for location l ----
        {
            const int g  = lane >> 2;
            const int t2 = (lane & 3) * 2;
            const float* bl = bias + (size_t)l * COUT;
            #pragma unroll
            for (int nt = 0; nt < 2; nt++) {
                const int c = warp * 16 + nt * 8 + t2;
                const float bv0 = bl[c];
                const float bv1 = bl[c + 1];
                #pragma unroll
                for (int mt = 0; mt < 2; mt++) {
                    const int b0 = mt * 16 + g;
                    out[((size_t)((b0    ) * COUT) + c    ) * LL + l] = acc[mt][nt][0] + bv0;
                    out[((size_t)((b0    ) * COUT) + c + 1) * LL + l] = acc[mt][nt][1] + bv1;
                    out[((size_t)((b0 + 8) * COUT) + c    ) * LL + l] = acc[mt][nt][2] + bv0;
                    out[((size_t)((b0 + 8) * COUT) + c + 1) * LL + l] = acc[mt][nt][3] + bv1;
                }
            }
        }
        __syncthreads();   // loc boundary: publish regions 0..8 for next loc
    }
}

extern "C" void kernel_launch(void* const* d_in, const int* in_sizes, int n_in,
                              void* d_out, int out_size)
{
    const float* x    = (const float*)d_in[0];   // [32,64,56,56]
    const float* w    = (const float*)d_in[1];   // [3136,64,576]
    const float* bias = (const float*)d_in[2];   // [3136,64]
    float* out        = (float*)d_out;           // [32,64,56,56]

    transpose_x<<<dim3(LL / 32, CIN / 32, BATCH), 256>>>(x);

    cudaFuncSetAttribute(lc2d_mma, cudaFuncAttributeMaxDynamicSharedMemorySize, SMEM_TOTAL);
    lc2d_mma<<<GRID, NTHREADS, SMEM_TOTAL>>>(w, bias, out);
}

// round 10
// speedup vs baseline: 1.0490x; 1.0490x over previous
#include <cuda_runtime.h>
#include <cstdint>

#define BATCH   32
#define CIN     64
#define COUT    64
#define HH      56
#define WW      56
#define LL      3136
#define FEAT    576
#define NCHUNK  18            // 576 / 32 f per chunk
#define NTHREADS 128          // 4 warps; warp tile = 16 batches x 16 channels
#define NSTAGE  8
#define DIST    7

// ---- smem ----
// patch: [16 b][580 floats] (tf32 bits), 2320B rows (odd x16 -> ldsm conflict-free)
#define PROW_BYTES  2320
#define NB          16                      // batches per CTA
#define PATCH_BYTES (NB * PROW_BYTES)       // 37120 (128B aligned)
// per-warp weight rings: 4 warps x 8 stages x [16 c][32 f] fp32 (2048 B)
#define WSTAGE_BYTES 2048
#define WRING_BYTES  (NSTAGE * WSTAGE_BYTES)     // 16384
#define RING_OFF     PATCH_BYTES
#define SMEM_TOTAL   (RING_OFF + 4 * WRING_BYTES)   // 102656

__device__ float g_xt[(size_t)BATCH * LL * CIN];

// ---------------- helpers ----------------
__device__ __forceinline__ uint32_t swz(uint32_t o) { return o ^ ((o >> 3) & 0x70); }

__device__ __forceinline__ uint32_t cvt_tf32(float v) {
    uint32_t t;
    asm("cvt.rna.tf32.f32 %0, %1;" : "=r"(t) : "f"(v));
    return t;
}
__device__ __forceinline__ uint32_t tf32r(uint32_t bits) {
    uint32_t t;
    asm("cvt.rna.tf32.f32 %0, %1;" : "=r"(t) : "f"(__uint_as_float(bits)));
    return t;
}

__device__ __forceinline__ void sts32(uint32_t a, uint32_t v) {
    asm volatile("st.shared.b32 [%0], %1;" :: "r"(a), "r"(v) : "memory");
}

__device__ __forceinline__ void cp_async16(uint32_t smem_addr, const void* gmem_ptr) {
    asm volatile("cp.async.cg.shared.global [%0], [%1], 16;\n"
                 :: "r"(smem_addr), "l"(gmem_ptr));
}

__device__ __forceinline__ void ldsm_x4(uint32_t addr, uint32_t& r0, uint32_t& r1,
                                        uint32_t& r2, uint32_t& r3) {
    asm volatile("ldmatrix.sync.aligned.m8n8.x4.shared.b16 {%0,%1,%2,%3}, [%4];"
                 : "=r"(r0), "=r"(r1), "=r"(r2), "=r"(r3) : "r"(addr));
}

__device__ __forceinline__ void mma_tf32(float* d, const uint32_t* a, const uint32_t* b) {
    asm volatile("mma.sync.aligned.m16n8k8.row.col.f32.tf32.tf32.f32 "
                 "{%0,%1,%2,%3}, {%4,%5,%6,%7}, {%8,%9}, {%0,%1,%2,%3};"
                 : "+f"(d[0]), "+f"(d[1]), "+f"(d[2]), "+f"(d[3])
                 : "r"(a[0]), "r"(a[1]), "r"(a[2]), "r"(a[3]),
                   "r"(b[0]), "r"(b[1]));
}

__device__ __forceinline__ void wait_rem(int n) {
    switch (n) {
        case 0: asm volatile("cp.async.wait_group 0;\n"); break;
        case 1: asm volatile("cp.async.wait_group 1;\n"); break;
        case 2: asm volatile("cp.async.wait_group 2;\n"); break;
        case 3: asm volatile("cp.async.wait_group 3;\n"); break;
        case 4: asm volatile("cp.async.wait_group 4;\n"); break;
        case 5: asm volatile("cp.async.wait_group 5;\n"); break;
        default: asm volatile("cp.async.wait_group 6;\n"); break;
    }
}

// ---------------- kernel 1: x NCHW -> NHWC transpose ----------------
__global__ void __launch_bounds__(256) transpose_x(const float* __restrict__ x) {
    __shared__ float tile[32][33];
    const int b  = blockIdx.z;
    const int c0 = blockIdx.y * 32;
    const int s0 = blockIdx.x * 32;
    const int tx = threadIdx.x & 31;
    const int ty = threadIdx.x >> 5;
    #pragma unroll
    for (int i = 0; i < 4; i++)
        tile[ty + 8 * i][tx] = x[((size_t)b * CIN + c0 + ty + 8 * i) * LL + s0 + tx];
    __syncthreads();
    #pragma unroll
    for (int i = 0; i < 4; i++)
        g_xt[((size_t)b * LL + s0 + ty + 8 * i) * CIN + c0 + tx] = tile[tx][ty + 8 * i];
}

// ---------------- kernel 2: per-(location, batch-half) GEMM ----------------
__global__ void __launch_bounds__(NTHREADS, 2)
lc2d_mma(const float* __restrict__ w,
         const float* __restrict__ bias,
         float* __restrict__ out)
{
    extern __shared__ char smem[];
    const uint32_t sb = (uint32_t)__cvta_generic_to_shared(smem);

    const int tid  = threadIdx.x;
    const int lane = tid & 31;
    const int warp = tid >> 5;        // 0..3, owns channels [16*warp, 16*warp+16)
    const int l    = blockIdx.x >> 1;
    const int half = blockIdx.x & 1;  // batch half: batches [16*half, 16*half+16)
    const int oh   = l / WW;
    const int ow   = l - oh * WW;

    const float* wl = w + (size_t)l * (COUT * FEAT);

    // warp-private weight ring
    const uint32_t wring = sb + RING_OFF + (uint32_t)warp * WRING_BYTES;

    // cp.async mapping: lane -> row = lane>>1 (0..15), fsel = lane&1
    const int wrow = lane >> 1;
    const int fsel = lane & 1;
    const float* wg = wl + (size_t)(warp * 16 + wrow) * FEAT + 4 * fsel;   // + k*32 + 8j
    const uint32_t wsd = (uint32_t)wrow * 128 + (uint32_t)fsel * 16;        // + j*32 (pre-swz)

    // ---- prologue: issue chunks 0..6 into stages 0..6 (per-warp groups) ----
    #pragma unroll
    for (int k = 0; k < DIST; k++) {
        const uint32_t st = wring + (uint32_t)k * WSTAGE_BYTES;
        #pragma unroll
        for (int j = 0; j < 4; j++)
            cp_async16(st + swz(wsd + (uint32_t)j * 32), wg + k * 32 + 8 * j);
        asm volatile("cp.async.commit_group;\n");
    }

    // ---- stage patches (16 batches) from g_xt ----
    {
        const int pos = tid & 15;                 // cin group: cin = pos*4 + q
        for (int s = tid >> 4; s < NB * 9; s += 8) {
            int b  = s / 9;                       // 0..15 (smem row)
            int rr = s - b * 9;                   // ki*3 + kj
            int ki = rr / 3, kj = rr - ki * 3;
            int h  = oh + ki - 1;
            int wq = ow + kj - 1;
            bool ok = ((unsigned)h < HH) & ((unsigned)wq < WW);
            float4 v = make_float4(0.f, 0.f, 0.f, 0.f);
            if (ok)
                v = *(const float4*)(g_xt + ((size_t)(half * NB + b) * LL + h * WW + wq) * CIN
                                     + pos * 4);
            // f = (pos*4+q)*9 + rr = 36*pos + 9q + rr
            uint32_t a = sb + (uint32_t)b * PROW_BYTES + (uint32_t)(36 * pos + rr) * 4;
            sts32(a,       cvt_tf32(v.x));
            sts32(a + 36,  cvt_tf32(v.y));
            sts32(a + 72,  cvt_tf32(v.z));
            sts32(a + 108, cvt_tf32(v.w));
        }
    }

    // ---- fragment addressing ----
    // A = patches (m16 = batches 0..15 of this half)
    const uint32_t a_base = sb + (uint32_t)(lane & 15) * PROW_BYTES
                          + ((lane & 16) ? 16u : 0u);
    // B = weights (n = 16 channels, 2 n-tiles via ldsm_x4)
    const uint32_t b_off = (uint32_t)((lane & 7) + ((lane & 16) ? 8 : 0)) * 128
                         + ((lane & 8) ? 16u : 0u);     // + ks*32, pre-swz

    float acc[2][4];
    #pragma unroll
    for (int nt = 0; nt < 2; nt++)
        #pragma unroll
        for (int q = 0; q < 4; q++) acc[nt][q] = 0.0f;

    __syncthreads();   // patch tile ready (only CTA-wide sync)

    // ---- main loop: no barriers; per-warp ring ----
    for (int k = 0; k < NCHUNK; k++) {
        // preload patch A-frags for chunk k (patch smem always ready)
        uint32_t a[4][4];
        #pragma unroll
        for (int ks = 0; ks < 4; ks++)
            ldsm_x4(a_base + (uint32_t)(k * 128 + ks * 32),
                    a[ks][0], a[ks][1], a[ks][2], a[ks][3]);

        if (k + DIST < NCHUNK) {
            // issue chunk k+7 into stage (k+7)&7 (WAR safe within warp)
            const uint32_t st = wring + (uint32_t)((k + DIST) & (NSTAGE - 1)) * WSTAGE_BYTES;
            const int f0 = (k + DIST) * 32;
            #pragma unroll
            for (int j = 0; j < 4; j++)
                cp_async16(st + swz(wsd + (uint32_t)j * 32), wg + f0 + 8 * j);
            asm volatile("cp.async.commit_group;\n");
            asm volatile("cp.async.wait_group %0;\n" :: "n"(DIST - 1));  // chunk k arrived
        } else {
            wait_rem(NCHUNK - 1 - k >= DIST - 1 ? DIST - 1 : NCHUNK - 1 - k);
        }

        const uint32_t wt = wring + (uint32_t)(k & (NSTAGE - 1)) * WSTAGE_BYTES;
        #pragma unroll
        for (int ks = 0; ks < 4; ks++) {
            uint32_t bf[4];
            ldsm_x4(wt + swz(b_off + (uint32_t)ks * 32), bf[0], bf[1], bf[2], bf[3]);
            #pragma unroll
            for (int q = 0; q < 4; q++) bf[q] = tf32r(bf[q]);
            mma_tf32(acc[0], a[ks], bf);        // channels warp*16 + 0..7
            mma_tf32(acc[1], a[ks], bf + 2);    // channels warp*16 + 8..15
        }
    }

    // ---- epilogue ----
    // D m16n8: rows = batch, cols = channel
    // d0=(g,2t) d1=(g,2t+1) d2=(g+8,2t) d3=(g+8,2t+1); g=lane>>2, t=lane&3
    const int g  = lane >> 2;
    const int t2 = (lane & 3) * 2;
    const float* bl = bias + (size_t)l * COUT;
    #pragma unroll
    for (int nt = 0; nt < 2; nt++) {
        const int c = warp * 16 + nt * 8 + t2;
        const float bv0 = bl[c];
        const float bv1 = bl[c + 1];
        const int b0 = half * NB + g;
        out[((size_t)((b0    ) * COUT) + c    ) * LL + l] = acc[nt][0] + bv0;
        out[((size_t)((b0    ) * COUT) + c + 1) * LL + l] = acc[nt][1] + bv1;
        out[((size_t)((b0 + 8) * COUT) + c    ) * LL + l] = acc[nt][2] + bv0;
        out[((size_t)((b0 + 8) * COUT) + c + 1) * LL + l] = acc[nt][3] + bv1;
    }
}

extern "C" void kernel_launch(void* const* d_in, const int* in_sizes, int n_in,
                              void* d_out, int out_size)
{
    const float* x    = (const float*)d_in[0];   // [32,64,56,56]
    const float* w    = (const float*)d_in[1];   // [3136,64,576]
    const float* bias = (const float*)d_in[2];   // [3136,64]
    float* out        = (float*)d_out;           // [32,64,56,56]

    transpose_x<<<dim3(LL / 32, CIN / 32, BATCH), 256>>>(x);

    cudaFuncSetAttribute(lc2d_mma, cudaFuncAttributeMaxDynamicSharedMemorySize, SMEM_TOTAL);
    lc2d_mma<<<LL * 2, NTHREADS, SMEM_TOTAL>>>(w, bias, out);
}

// round 11
// speedup vs baseline: 1.1197x; 1.0674x over previous
#include <cuda_runtime.h>
#include <cuda.h>
#include <cstdint>

#define BATCH   32
#define CIN     64
#define COUT    64
#define HH      56
#define WW      56
#define LL      3136
#define FEAT    576
#define NCHUNK  18            // 576 / 32 f per chunk
#define NTHREADS 128          // 4 warps; warp tile = 16 batches x 16 channels
#define NSTAGE  9
#define DIST    8

// ---- smem ----
// patch: [16 b][580 floats] (tf32 bits), 2320B rows (odd x16 -> ldsm conflict-free)
#define PROW_BYTES  2320
#define NB          16                      // batches per CTA
#define PATCH_BYTES (NB * PROW_BYTES)       // 37120
// per-warp TMA weight rings: 4 warps x 9 stages x [16 c][32 f] fp32 (2048 B)
// ring base 1024-aligned for SW128 TMA tiles
#define RING_OFF     37888
#define WSTAGE_BYTES 2048
#define WRING_BYTES  (NSTAGE * WSTAGE_BYTES)        // 18432
#define MBAR_OFF     (RING_OFF + 4 * WRING_BYTES)   // 111616; 4*9 mbars
#define SMEM_TOTAL   (MBAR_OFF + 4 * NSTAGE * 8)    // 111904

__device__ float g_xt[(size_t)BATCH * LL * CIN];

// ---------------- helpers ----------------
__device__ __forceinline__ uint32_t swz(uint32_t o) { return o ^ ((o >> 3) & 0x70); }

__device__ __forceinline__ uint32_t cvt_tf32(float v) {
    uint32_t t;
    asm("cvt.rna.tf32.f32 %0, %1;" : "=r"(t) : "f"(v));
    return t;
}
__device__ __forceinline__ uint32_t tf32r(uint32_t bits) {
    uint32_t t;
    asm("cvt.rna.tf32.f32 %0, %1;" : "=r"(t) : "f"(__uint_as_float(bits)));
    return t;
}

__device__ __forceinline__ void sts32(uint32_t a, uint32_t v) {
    asm volatile("st.shared.b32 [%0], %1;" :: "r"(a), "r"(v) : "memory");
}

__device__ __forceinline__ void ldsm_x4(uint32_t addr, uint32_t& r0, uint32_t& r1,
                                        uint32_t& r2, uint32_t& r3) {
    asm volatile("ldmatrix.sync.aligned.m8n8.x4.shared.b16 {%0,%1,%2,%3}, [%4];"
                 : "=r"(r0), "=r"(r1), "=r"(r2), "=r"(r3) : "r"(addr));
}

__device__ __forceinline__ void mma_tf32(float* d, const uint32_t* a, const uint32_t* b) {
    asm volatile("mma.sync.aligned.m16n8k8.row.col.f32.tf32.tf32.f32 "
                 "{%0,%1,%2,%3}, {%4,%5,%6,%7}, {%8,%9}, {%0,%1,%2,%3};"
                 : "+f"(d[0]), "+f"(d[1]), "+f"(d[2]), "+f"(d[3])
                 : "r"(a[0]), "r"(a[1]), "r"(a[2]), "r"(a[3]),
                   "r"(b[0]), "r"(b[1]));
}

__device__ __forceinline__ uint32_t elect1() {
    uint32_t p;
    asm volatile("{\n\t.reg .pred p;\n\telect.sync _|p, 0xFFFFFFFF;\n\tselp.b32 %0, 1, 0, p;\n\t}"
                 : "=r"(p));
    return p;
}

__device__ __forceinline__ void mbar_init(uint32_t mbar, uint32_t cnt) {
    asm volatile("mbarrier.init.shared.b64 [%0], %1;" :: "r"(mbar), "r"(cnt) : "memory");
}
__device__ __forceinline__ void mbar_expect_tx(uint32_t mbar, uint32_t bytes) {
    asm volatile("mbarrier.arrive.expect_tx.shared.b64 _, [%0], %1;"
                 :: "r"(mbar), "r"(bytes) : "memory");
}
__device__ __forceinline__ void mbar_wait(uint32_t mbar, uint32_t parity) {
    asm volatile("{\n\t.reg .pred P;\n\t"
                 "WL_%=:\n\t"
                 "mbarrier.try_wait.parity.acquire.cta.shared::cta.b64 P, [%0], %1, 0x989680;\n\t"
                 "@P bra.uni WD_%=;\n\t"
                 "bra.uni WL_%=;\n\t"
                 "WD_%=:\n\t}"
                 :: "r"(mbar), "r"(parity) : "memory");
}

__device__ __forceinline__ void tma_2d(uint32_t smem_dst, const void* tmap,
                                       int x, int y, uint32_t mbar) {
    asm volatile("cp.async.bulk.tensor.2d.shared::cta.global.tile.mbarrier::complete_tx::bytes "
                 "[%0], [%1, {%2, %3}], [%4];"
                 :: "r"(smem_dst), "l"(tmap), "r"(x), "r"(y), "r"(mbar) : "memory");
}

// ---------------- kernel 1: x NCHW -> NHWC transpose ----------------
__global__ void __launch_bounds__(256) transpose_x(const float* __restrict__ x) {
    __shared__ float tile[32][33];
    const int b  = blockIdx.z;
    const int c0 = blockIdx.y * 32;
    const int s0 = blockIdx.x * 32;
    const int tx = threadIdx.x & 31;
    const int ty = threadIdx.x >> 5;
    #pragma unroll
    for (int i = 0; i < 4; i++)
        tile[ty + 8 * i][tx] = x[((size_t)b * CIN + c0 + ty + 8 * i) * LL + s0 + tx];
    __syncthreads();
    #pragma unroll
    for (int i = 0; i < 4; i++)
        g_xt[((size_t)b * LL + s0 + ty + 8 * i) * CIN + c0 + tx] = tile[tx][ty + 8 * i];
}

// ---------------- kernel 2: per-(location, batch-half) GEMM, TMA weights ----------------
__global__ void __launch_bounds__(NTHREADS, 2)
lc2d_mma(const __grid_constant__ CUtensorMap wmap,
         const float* __restrict__ bias,
         float* __restrict__ out)
{
    extern __shared__ __align__(1024) char smem[];
    const uint32_t sb = (uint32_t)__cvta_generic_to_shared(smem);

    const int tid  = threadIdx.x;
    const int lane = tid & 31;
    const int warp = tid >> 5;        // 0..3, owns channels [16*warp, 16*warp+16)
    const int l    = blockIdx.x >> 1;
    const int half = blockIdx.x & 1;  // batches [16*half, 16*half+16)
    const int oh   = l / WW;
    const int ow   = l - oh * WW;

    const uint32_t wring = sb + RING_OFF + (uint32_t)warp * WRING_BYTES;
    const uint32_t wmbar = sb + MBAR_OFF + (uint32_t)warp * (NSTAGE * 8);
    const int      yrow  = l * COUT + warp * 16;   // weight row block for this warp

    // ---- init mbarriers ----
    if (tid == 0) {
        #pragma unroll
        for (int i = 0; i < 4 * NSTAGE; i++)
            mbar_init(sb + MBAR_OFF + (uint32_t)i * 8, 1);
    }
    __syncthreads();

    // ---- prologue: issue weight chunks 0..7 into stages 0..7 (elected lane) ----
    if (elect1()) {
        #pragma unroll
        for (int k = 0; k < DIST; k++) {
            mbar_expect_tx(wmbar + (uint32_t)k * 8, WSTAGE_BYTES);
            tma_2d(wring + (uint32_t)k * WSTAGE_BYTES, &wmap, k * 32, yrow,
                   wmbar + (uint32_t)k * 8);
        }
    }

    // ---- stage patches (16 batches) from g_xt ----
    {
        const int pos = tid & 15;                 // cin group: cin = pos*4 + q
        for (int s = tid >> 4; s < NB * 9; s += 8) {
            int b  = s / 9;                       // 0..15 (smem row)
            int rr = s - b * 9;                   // ki*3 + kj
            int ki = rr / 3, kj = rr - ki * 3;
            int h  = oh + ki - 1;
            int wq = ow + kj - 1;
            bool ok = ((unsigned)h < HH) & ((unsigned)wq < WW);
            float4 v = make_float4(0.f, 0.f, 0.f, 0.f);
            if (ok)
                v = *(const float4*)(g_xt + ((size_t)(half * NB + b) * LL + h * WW + wq) * CIN
                                     + pos * 4);
            // f = (pos*4+q)*9 + rr = 36*pos + 9q + rr
            uint32_t a = sb + (uint32_t)b * PROW_BYTES + (uint32_t)(36 * pos + rr) * 4;
            sts32(a,       cvt_tf32(v.x));
            sts32(a + 36,  cvt_tf32(v.y));
            sts32(a + 72,  cvt_tf32(v.z));
            sts32(a + 108, cvt_tf32(v.w));
        }
    }

    // ---- fragment addressing ----
    // A = patches (m16 = batches 0..15 of this half)
    const uint32_t a_base = sb + (uint32_t)(lane & 15) * PROW_BYTES
                          + ((lane & 16) ? 16u : 0u);
    // B = weights (n = 16 channels, 2 n-tiles via ldsm_x4) on [16c][32f] swizzled tile
    const uint32_t b_off = (uint32_t)((lane & 7) + ((lane & 16) ? 8 : 0)) * 128
                         + ((lane & 8) ? 16u : 0u);     // + ks*32, pre-swz

    float acc[2][4];
    #pragma unroll
    for (int nt = 0; nt < 2; nt++)
        #pragma unroll
        for (int q = 0; q < 4; q++) acc[nt][q] = 0.0f;

    __syncthreads();   // patch tile ready (only CTA-wide sync after init)

    // ---- main loop: no CTA barriers; per-warp TMA ring ----
    for (int k = 0; k < NCHUNK; k++) {
        // preload patch A-frags for chunk k
        uint32_t a[4][4];
        #pragma unroll
        for (int ks = 0; ks < 4; ks++)
            ldsm_x4(a_base + (uint32_t)(k * 128 + ks * 32),
                    a[ks][0], a[ks][1], a[ks][2], a[ks][3]);

        // wait for chunk k's weights (slot k%9, parity = k/9)
        const int slot = (k < NSTAGE) ? k : k - NSTAGE;
        mbar_wait(wmbar + (uint32_t)slot * 8, (k < NSTAGE) ? 0u : 1u);

        // issue chunk k+8 into slot (k+8)%9 (that slot's data was consumed at k-1)
        if (k + DIST < NCHUNK && elect1()) {
            const int ks2  = k + DIST;
            const int slot2 = (ks2 < NSTAGE) ? ks2 : ks2 - NSTAGE;
            mbar_expect_tx(wmbar + (uint32_t)slot2 * 8, WSTAGE_BYTES);
            tma_2d(wring + (uint32_t)slot2 * WSTAGE_BYTES, &wmap, ks2 * 32, yrow,
                   wmbar + (uint32_t)slot2 * 8);
        }

        const uint32_t wt = wring + (uint32_t)slot * WSTAGE_BYTES;
        #pragma unroll
        for (int ks = 0; ks < 4; ks++) {
            uint32_t bf[4];
            ldsm_x4(wt + swz(b_off + (uint32_t)ks * 32), bf[0], bf[1], bf[2], bf[3]);
            #pragma unroll
            for (int q = 0; q < 4; q++) bf[q] = tf32r(bf[q]);
            mma_tf32(acc[0], a[ks], bf);        // channels warp*16 + 0..7
            mma_tf32(acc[1], a[ks], bf + 2);    // channels warp*16 + 8..15
        }
    }

    // ---- epilogue ----
    const int g  = lane >> 2;
    const int t2 = (lane & 3) * 2;
    const float* bl = bias + (size_t)l * COUT;
    #pragma unroll
    for (int nt = 0; nt < 2; nt++) {
        const int c = warp * 16 + nt * 8 + t2;
        const float bv0 = bl[c];
        const float bv1 = bl[c + 1];
        const int b0 = half * NB + g;
        out[((size_t)((b0    ) * COUT) + c    ) * LL + l] = acc[nt][0] + bv0;
        out[((size_t)((b0    ) * COUT) + c + 1) * LL + l] = acc[nt][1] + bv1;
        out[((size_t)((b0 + 8) * COUT) + c    ) * LL + l] = acc[nt][2] + bv0;
        out[((size_t)((b0 + 8) * COUT) + c + 1) * LL + l] = acc[nt][3] + bv1;
    }
}

// ---------------- host ----------------
typedef CUresult (*EncodeTiledFn)(
    CUtensorMap*, CUtensorMapDataType, cuuint32_t, void*,
    const cuuint64_t*, const cuuint64_t*, const cuuint32_t*, const cuuint32_t*,
    CUtensorMapInterleave, CUtensorMapSwizzle, CUtensorMapL2promotion,
    CUtensorMapFloatOOBfill);

extern "C" void kernel_launch(void* const* d_in, const int* in_sizes, int n_in,
                              void* d_out, int out_size)
{
    const float* x    = (const float*)d_in[0];   // [32,64,56,56]
    const float* w    = (const float*)d_in[1];   // [3136,64,576]
    const float* bias = (const float*)d_in[2];   // [3136,64]
    float* out        = (float*)d_out;           // [32,64,56,56]

    // weight tensor map: 2D [576 f][200704 rows = c + 64*l], box [32, 16], SW128
    void* fp = nullptr;
    cudaDriverEntryPointQueryResult qr;
    cudaGetDriverEntryPointByVersion("cuTensorMapEncodeTiled", &fp, 12000,
                                     cudaEnableDefault, &qr);
    EncodeTiledFn encode = (EncodeTiledFn)fp;

    CUtensorMap wmap;
    cuuint64_t dims[2]    = {(cuuint64_t)FEAT, (cuuint64_t)LL * COUT};
    cuuint64_t strides[1] = {(cuuint64_t)FEAT * sizeof(float)};
    cuuint32_t box[2]     = {32, 16};
    cuuint32_t estr[2]    = {1, 1};
    encode(&wmap, CU_TENSOR_MAP_DATA_TYPE_FLOAT32, 2, (void*)w,
           dims, strides, box, estr,
           CU_TENSOR_MAP_INTERLEAVE_NONE, CU_TENSOR_MAP_SWIZZLE_128B,
           CU_TENSOR_MAP_L2_PROMOTION_L2_128B, CU_TENSOR_MAP_FLOAT_OOB_FILL_NONE);

    transpose_x<<<dim3(LL / 32, CIN / 32, BATCH), 256>>>(x);

    cudaFuncSetAttribute(lc2d_mma, cudaFuncAttributeMaxDynamicSharedMemorySize, SMEM_TOTAL);
    lc2d_mma<<<LL * 2, NTHREADS, SMEM_TOTAL>>>(wmap, bias, out);
}

// round 12
// speedup vs baseline: 1.3516x; 1.2071x over previous
#include <cuda_runtime.h>
#include <cuda.h>
#include <cstdint>

#define BATCH   32
#define CIN     64
#define COUT    64
#define HH      56
#define WW      56
#define LL      3136
#define FEAT    576
#define NCHUNK  18            // 576 / 32 f per chunk
#define NTHREADS 256          // 8 warps; warp tile = 16 batches x 8 channels
#define NWARP   8
#define NSTAGE  9
#define DIST    8

// ---- smem ----
// patch: [16 b][580 floats] (tf32 bits), 2320B rows (odd x16 -> ldsm conflict-free)
#define PROW_BYTES  2320
#define NB          16                      // batches per CTA
#define PATCH_BYTES (NB * PROW_BYTES)       // 37120
// per-warp TMA weight rings: 8 warps x 9 stages x [8 c][32 f] fp32 (1024 B)
#define RING_OFF     37888                  // 1024-aligned
#define WSTAGE_BYTES 1024
#define WRING_BYTES  (NSTAGE * WSTAGE_BYTES)        // 9216
#define MBAR_OFF     (RING_OFF + NWARP * WRING_BYTES)   // 111616
#define SMEM_TOTAL   (MBAR_OFF + NWARP * NSTAGE * 8)    // 112192

__device__ float g_xt[(size_t)BATCH * LL * CIN];

// ---------------- helpers ----------------
__device__ __forceinline__ uint32_t swz(uint32_t o) { return o ^ ((o >> 3) & 0x70); }

__device__ __forceinline__ uint32_t cvt_tf32(float v) {
    uint32_t t;
    asm("cvt.rna.tf32.f32 %0, %1;" : "=r"(t) : "f"(v));
    return t;
}
__device__ __forceinline__ uint32_t tf32r(uint32_t bits) {
    uint32_t t;
    asm("cvt.rna.tf32.f32 %0, %1;" : "=r"(t) : "f"(__uint_as_float(bits)));
    return t;
}

__device__ __forceinline__ void sts32(uint32_t a, uint32_t v) {
    asm volatile("st.shared.b32 [%0], %1;" :: "r"(a), "r"(v) : "memory");
}

__device__ __forceinline__ void ldsm_x4(uint32_t addr, uint32_t& r0, uint32_t& r1,
                                        uint32_t& r2, uint32_t& r3) {
    asm volatile("ldmatrix.sync.aligned.m8n8.x4.shared.b16 {%0,%1,%2,%3}, [%4];"
                 : "=r"(r0), "=r"(r1), "=r"(r2), "=r"(r3) : "r"(addr));
}
__device__ __forceinline__ void ldsm_x2(uint32_t addr, uint32_t& r0, uint32_t& r1) {
    asm volatile("ldmatrix.sync.aligned.m8n8.x2.shared.b16 {%0,%1}, [%2];"
                 : "=r"(r0), "=r"(r1) : "r"(addr));
}

__device__ __forceinline__ void mma_tf32(float* d, const uint32_t* a, const uint32_t* b) {
    asm volatile("mma.sync.aligned.m16n8k8.row.col.f32.tf32.tf32.f32 "
                 "{%0,%1,%2,%3}, {%4,%5,%6,%7}, {%8,%9}, {%0,%1,%2,%3};"
                 : "+f"(d[0]), "+f"(d[1]), "+f"(d[2]), "+f"(d[3])
                 : "r"(a[0]), "r"(a[1]), "r"(a[2]), "r"(a[3]),
                   "r"(b[0]), "r"(b[1]));
}

__device__ __forceinline__ uint32_t elect1() {
    uint32_t p;
    asm volatile("{\n\t.reg .pred p;\n\telect.sync _|p, 0xFFFFFFFF;\n\tselp.b32 %0, 1, 0, p;\n\t}"
                 : "=r"(p));
    return p;
}

__device__ __forceinline__ void mbar_init(uint32_t mbar, uint32_t cnt) {
    asm volatile("mbarrier.init.shared.b64 [%0], %1;" :: "r"(mbar), "r"(cnt) : "memory");
}
__device__ __forceinline__ void mbar_expect_tx(uint32_t mbar, uint32_t bytes) {
    asm volatile("mbarrier.arrive.expect_tx.shared.b64 _, [%0], %1;"
                 :: "r"(mbar), "r"(bytes) : "memory");
}
__device__ __forceinline__ void mbar_wait(uint32_t mbar, uint32_t parity) {
    asm volatile("{\n\t.reg .pred P;\n\t"
                 "WL_%=:\n\t"
                 "mbarrier.try_wait.parity.acquire.cta.shared::cta.b64 P, [%0], %1, 0x989680;\n\t"
                 "@P bra.uni WD_%=;\n\t"
                 "bra.uni WL_%=;\n\t"
                 "WD_%=:\n\t}"
                 :: "r"(mbar), "r"(parity) : "memory");
}

__device__ __forceinline__ void tma_2d(uint32_t smem_dst, const void* tmap,
                                       int x, int y, uint32_t mbar) {
    asm volatile("cp.async.bulk.tensor.2d.shared::cta.global.tile.mbarrier::complete_tx::bytes "
                 "[%0], [%1, {%2, %3}], [%4];"
                 :: "r"(smem_dst), "l"(tmap), "r"(x), "r"(y), "r"(mbar) : "memory");
}

// ---------------- kernel 1: x NCHW -> NHWC transpose ----------------
__global__ void __launch_bounds__(256) transpose_x(const float* __restrict__ x) {
    __shared__ float tile[32][33];
    const int b  = blockIdx.z;
    const int c0 = blockIdx.y * 32;
    const int s0 = blockIdx.x * 32;
    const int tx = threadIdx.x & 31;
    const int ty = threadIdx.x >> 5;
    #pragma unroll
    for (int i = 0; i < 4; i++)
        tile[ty + 8 * i][tx] = x[((size_t)b * CIN + c0 + ty + 8 * i) * LL + s0 + tx];
    __syncthreads();
    #pragma unroll
    for (int i = 0; i < 4; i++)
        g_xt[((size_t)b * LL + s0 + ty + 8 * i) * CIN + c0 + tx] = tile[tx][ty + 8 * i];
}

// ---------------- kernel 2: per-(location, batch-half) GEMM, TMA weights ----------------
__global__ void __launch_bounds__(NTHREADS, 2)
lc2d_mma(const __grid_constant__ CUtensorMap wmap,
         const float* __restrict__ bias,
         float* __restrict__ out)
{
    extern __shared__ __align__(1024) char smem[];
    const uint32_t sb = (uint32_t)__cvta_generic_to_shared(smem);

    const int tid  = threadIdx.x;
    const int lane = tid & 31;
    const int warp = tid >> 5;        // 0..7, owns channels [8*warp, 8*warp+8)
    const int l    = blockIdx.x >> 1;
    const int half = blockIdx.x & 1;  // batches [16*half, 16*half+16)
    const int oh   = l / WW;
    const int ow   = l - oh * WW;

    const uint32_t wring = sb + RING_OFF + (uint32_t)warp * WRING_BYTES;
    const uint32_t wmbar = sb + MBAR_OFF + (uint32_t)warp * (NSTAGE * 8);
    const int      yrow  = l * COUT + warp * 8;   // weight row block for this warp

    // ---- init mbarriers ----
    if (tid < NWARP * NSTAGE)
        mbar_init(sb + MBAR_OFF + (uint32_t)tid * 8, 1);
    __syncthreads();

    // ---- prologue: issue weight chunks 0..7 into stages 0..7 (elected lane/warp) ----
    if (elect1()) {
        #pragma unroll
        for (int k = 0; k < DIST; k++) {
            mbar_expect_tx(wmbar + (uint32_t)k * 8, WSTAGE_BYTES);
            tma_2d(wring + (uint32_t)k * WSTAGE_BYTES, &wmap, k * 32, yrow,
                   wmbar + (uint32_t)k * 8);
        }
    }

    // ---- stage patches (16 batches): front-loaded LDGs for MLP ----
    {
        const int pos = tid & 15;                 // cin group: cin = pos*4 + q
        float4   v[9];
        uint32_t adr[9];
        #pragma unroll
        for (int i = 0; i < 9; i++) {
            int s  = (tid >> 4) + i * 16;         // 0..143
            int b  = s / 9;
            int rr = s - b * 9;                   // ki*3 + kj
            int ki = rr / 3, kj = rr - ki * 3;
            int h  = oh + ki - 1;
            int wq = ow + kj - 1;
            bool ok = ((unsigned)h < HH) & ((unsigned)wq < WW);
            v[i] = make_float4(0.f, 0.f, 0.f, 0.f);
            if (ok)
                v[i] = *(const float4*)(g_xt + ((size_t)(half * NB + b) * LL + h * WW + wq) * CIN
                                        + pos * 4);
            // f = (pos*4+q)*9 + rr = 36*pos + 9q + rr
            adr[i] = sb + (uint32_t)b * PROW_BYTES + (uint32_t)(36 * pos + rr) * 4;
        }
        #pragma unroll
        for (int i = 0; i < 9; i++) {
            sts32(adr[i],       cvt_tf32(v[i].x));
            sts32(adr[i] + 36,  cvt_tf32(v[i].y));
            sts32(adr[i] + 72,  cvt_tf32(v[i].z));
            sts32(adr[i] + 108, cvt_tf32(v[i].w));
        }
    }

    // ---- fragment addressing ----
    // A = patches (m16 = batches 0..15 of this half)
    const uint32_t a_base = sb + (uint32_t)(lane & 15) * PROW_BYTES
                          + ((lane & 16) ? 16u : 0u);
    // B = weights (n8 = this warp's 8 channels) on [8c][32f] swizzled 1KB tile
    // ldsm_x2 uses lanes 0..15: row = lane&7, k-half by lane&8
    const uint32_t b_off = (uint32_t)(lane & 7) * 128 + ((lane & 8) ? 16u : 0u);  // + ks*32, pre-swz

    float acc[4];
    #pragma unroll
    for (int q = 0; q < 4; q++) acc[q] = 0.0f;

    __syncthreads();   // patch tile ready

    // ---- main loop: no CTA barriers; per-warp TMA ring ----
    for (int k = 0; k < NCHUNK; k++) {
        // preload patch A-frags for chunk k
        uint32_t a[4][4];
        #pragma unroll
        for (int ks = 0; ks < 4; ks++)
            ldsm_x4(a_base + (uint32_t)(k * 128 + ks * 32),
                    a[ks][0], a[ks][1], a[ks][2], a[ks][3]);

        // wait for chunk k's weights (slot k%9, parity = k/9)
        const int slot = (k < NSTAGE) ? k : k - NSTAGE;
        mbar_wait(wmbar + (uint32_t)slot * 8, (k < NSTAGE) ? 0u : 1u);

        // issue chunk k+8 into slot (k+8)%9 (that slot was consumed at k-1)
        if (k + DIST < NCHUNK && elect1()) {
            const int kn    = k + DIST;
            const int slot2 = (kn < NSTAGE) ? kn : kn - NSTAGE;
            mbar_expect_tx(wmbar + (uint32_t)slot2 * 8, WSTAGE_BYTES);
            tma_2d(wring + (uint32_t)slot2 * WSTAGE_BYTES, &wmap, kn * 32, yrow,
                   wmbar + (uint32_t)slot2 * 8);
        }

        const uint32_t wt = wring + (uint32_t)slot * WSTAGE_BYTES;
        #pragma unroll
        for (int ks = 0; ks < 4; ks++) {
            uint32_t bf[2];
            ldsm_x2(wt + swz(b_off + (uint32_t)ks * 32), bf[0], bf[1]);
            bf[0] = tf32r(bf[0]);
            bf[1] = tf32r(bf[1]);
            mma_tf32(acc, a[ks], bf);
        }
    }

    // ---- epilogue ----
    // D m16n8: rows = batch, cols = channel
    // d0=(g,2t) d1=(g,2t+1) d2=(g+8,2t) d3=(g+8,2t+1); g=lane>>2, t=lane&3
    const int g  = lane >> 2;
    const int t2 = (lane & 3) * 2;
    const int c  = warp * 8 + t2;
    const float* bl = bias + (size_t)l * COUT;
    const float bv0 = bl[c];
    const float bv1 = bl[c + 1];
    const int b0 = half * NB + g;
    out[((size_t)((b0    ) * COUT) + c    ) * LL + l] = acc[0] + bv0;
    out[((size_t)((b0    ) * COUT) + c + 1) * LL + l] = acc[1] + bv1;
    out[((size_t)((b0 + 8) * COUT) + c    ) * LL + l] = acc[2] + bv0;
    out[((size_t)((b0 + 8) * COUT) + c + 1) * LL + l] = acc[3] + bv1;
}

// ---------------- host ----------------
typedef CUresult (*EncodeTiledFn)(
    CUtensorMap*, CUtensorMapDataType, cuuint32_t, void*,
    const cuuint64_t*, const cuuint64_t*, const cuuint32_t*, const cuuint32_t*,
    CUtensorMapInterleave, CUtensorMapSwizzle, CUtensorMapL2promotion,
    CUtensorMapFloatOOBfill);

extern "C" void kernel_launch(void* const* d_in, const int* in_sizes, int n_in,
                              void* d_out, int out_size)
{
    const float* x    = (const float*)d_in[0];   // [32,64,56,56]
    const float* w    = (const float*)d_in[1];   // [3136,64,576]
    const float* bias = (const float*)d_in[2];   // [3136,64]
    float* out        = (float*)d_out;           // [32,64,56,56]

    // weight tensor map: 2D [576 f][200704 rows = c + 64*l], box [32, 8], SW128
    void* fp = nullptr;
    cudaDriverEntryPointQueryResult qr;
    cudaGetDriverEntryPointByVersion("cuTensorMapEncodeTiled", &fp, 12000,
                                     cudaEnableDefault, &qr);
    EncodeTiledFn encode = (EncodeTiledFn)fp;

    CUtensorMap wmap;
    cuuint64_t dims[2]    = {(cuuint64_t)FEAT, (cuuint64_t)LL * COUT};
    cuuint64_t strides[1] = {(cuuint64_t)FEAT * sizeof(float)};
    cuuint32_t box[2]     = {32, 8};
    cuuint32_t estr[2]    = {1, 1};
    encode(&wmap, CU_TENSOR_MAP_DATA_TYPE_FLOAT32, 2, (void*)w,
           dims, strides, box, estr,
           CU_TENSOR_MAP_INTERLEAVE_NONE, CU_TENSOR_MAP_SWIZZLE_128B,
           CU_TENSOR_MAP_L2_PROMOTION_L2_128B, CU_TENSOR_MAP_FLOAT_OOB_FILL_NONE);

    transpose_x<<<dim3(LL / 32, CIN / 32, BATCH), 256>>>(x);

    cudaFuncSetAttribute(lc2d_mma, cudaFuncAttributeMaxDynamicSharedMemorySize, SMEM_TOTAL);
    lc2d_mma<<<LL * 2, NTHREADS, SMEM_TOTAL>>>(wmap, bias, out);
}

// round 13
// speedup vs baseline: 1.8505x; 1.3691x over previous
#include <cuda_runtime.h>
#include <cuda.h>
#include <cstdint>

#define BATCH   32
#define CIN     64
#define COUT    64
#define HH      56
#define WW      56
#define LL      3136
#define FEAT    576
#define NCHUNK  18            // 576 / 32 f
#define KHALF   9             // chunks per k-half
#define NTHREADS 256          // 8 warps = 4 channel-groups x 2 k-halves
#define NWARP   8
#define NSTAGE  4
#define DIST    3

// ---- smem ----
// patch: [16 b][580 floats] (tf32 bits), 2320B rows (odd x16 -> ldsm conflict-free)
#define PROW_BYTES  2320
#define NB          16
#define PATCH_BYTES (NB * PROW_BYTES)       // 37120
// per-warp TMA weight rings: 8 warps x 4 stages x [16 c][32 f] fp32 (2048 B)
#define RING_OFF     37888                  // 1024-aligned
#define WSTAGE_BYTES 2048
#define WRING_BYTES  (NSTAGE * WSTAGE_BYTES)            // 8192
#define MBAR_OFF     (RING_OFF + NWARP * WRING_BYTES)   // 103424
#define SMEM_TOTAL   (MBAR_OFF + NWARP * NSTAGE * 8)    // 103680

__device__ float g_xt[(size_t)BATCH * LL * CIN];

// ---------------- helpers ----------------
__device__ __forceinline__ uint32_t swz(uint32_t o) { return o ^ ((o >> 3) & 0x70); }

__device__ __forceinline__ uint32_t cvt_tf32(float v) {
    uint32_t t;
    asm("cvt.rna.tf32.f32 %0, %1;" : "=r"(t) : "f"(v));
    return t;
}
__device__ __forceinline__ uint32_t tf32r(uint32_t bits) {
    uint32_t t;
    asm("cvt.rna.tf32.f32 %0, %1;" : "=r"(t) : "f"(__uint_as_float(bits)));
    return t;
}

__device__ __forceinline__ void sts32(uint32_t a, uint32_t v) {
    asm volatile("st.shared.b32 [%0], %1;" :: "r"(a), "r"(v) : "memory");
}

__device__ __forceinline__ void ldsm_x4(uint32_t addr, uint32_t& r0, uint32_t& r1,
                                        uint32_t& r2, uint32_t& r3) {
    asm volatile("ldmatrix.sync.aligned.m8n8.x4.shared.b16 {%0,%1,%2,%3}, [%4];"
                 : "=r"(r0), "=r"(r1), "=r"(r2), "=r"(r3) : "r"(addr));
}

__device__ __forceinline__ void mma_tf32(float* d, const uint32_t* a, const uint32_t* b) {
    asm volatile("mma.sync.aligned.m16n8k8.row.col.f32.tf32.tf32.f32 "
                 "{%0,%1,%2,%3}, {%4,%5,%6,%7}, {%8,%9}, {%0,%1,%2,%3};"
                 : "+f"(d[0]), "+f"(d[1]), "+f"(d[2]), "+f"(d[3])
                 : "r"(a[0]), "r"(a[1]), "r"(a[2]), "r"(a[3]),
                   "r"(b[0]), "r"(b[1]));
}

__device__ __forceinline__ uint32_t elect1() {
    uint32_t p;
    asm volatile("{\n\t.reg .pred p;\n\telect.sync _|p, 0xFFFFFFFF;\n\tselp.b32 %0, 1, 0, p;\n\t}"
                 : "=r"(p));
    return p;
}

__device__ __forceinline__ void mbar_init(uint32_t mbar, uint32_t cnt) {
    asm volatile("mbarrier.init.shared.b64 [%0], %1;" :: "r"(mbar), "r"(cnt) : "memory");
}
__device__ __forceinline__ void mbar_expect_tx(uint32_t mbar, uint32_t bytes) {
    asm volatile("mbarrier.arrive.expect_tx.shared.b64 _, [%0], %1;"
                 :: "r"(mbar), "r"(bytes) : "memory");
}
__device__ __forceinline__ void mbar_wait(uint32_t mbar, uint32_t parity) {
    asm volatile("{\n\t.reg .pred P;\n\t"
                 "WL_%=:\n\t"
                 "mbarrier.try_wait.parity.acquire.cta.shared::cta.b64 P, [%0], %1, 0x989680;\n\t"
                 "@P bra.uni WD_%=;\n\t"
                 "bra.uni WL_%=;\n\t"
                 "WD_%=:\n\t}"
                 :: "r"(mbar), "r"(parity) : "memory");
}

__device__ __forceinline__ void tma_2d(uint32_t smem_dst, const void* tmap,
                                       int x, int y, uint32_t mbar) {
    asm volatile("cp.async.bulk.tensor.2d.shared::cta.global.tile.mbarrier::complete_tx::bytes "
                 "[%0], [%1, {%2, %3}], [%4];"
                 :: "r"(smem_dst), "l"(tmap), "r"(x), "r"(y), "r"(mbar) : "memory");
}

// ---------------- kernel 1: x NCHW -> NHWC transpose ----------------
__global__ void __launch_bounds__(256) transpose_x(const float* __restrict__ x) {
    __shared__ float tile[32][33];
    const int b  = blockIdx.z;
    const int c0 = blockIdx.y * 32;
    const int s0 = blockIdx.x * 32;
    const int tx = threadIdx.x & 31;
    const int ty = threadIdx.x >> 5;
    #pragma unroll
    for (int i = 0; i < 4; i++)
        tile[ty + 8 * i][tx] = x[((size_t)b * CIN + c0 + ty + 8 * i) * LL + s0 + tx];
    __syncthreads();
    #pragma unroll
    for (int i = 0; i < 4; i++)
        g_xt[((size_t)b * LL + s0 + ty + 8 * i) * CIN + c0 + tx] = tile[tx][ty + 8 * i];
}

// ---------------- kernel 2: per-(location, batch-half) GEMM, k-split warps ----------------
__global__ void __launch_bounds__(NTHREADS, 2)
lc2d_mma(const __grid_constant__ CUtensorMap wmap,
         const float* __restrict__ bias,
         float* __restrict__ out)
{
    extern __shared__ __align__(1024) char smem[];
    const uint32_t sb = (uint32_t)__cvta_generic_to_shared(smem);

    const int tid  = threadIdx.x;
    const int lane = tid & 31;
    const int warp = tid >> 5;
    const int kh   = warp & 1;        // k half: chunks [9*kh, 9*kh+9)
    const int cg   = warp >> 1;       // channel group: channels [16*cg, 16*cg+16)
    const int l    = blockIdx.x >> 1;
    const int half = blockIdx.x & 1;  // batches [16*half, 16*half+16)
    const int oh   = l / WW;
    const int ow   = l - oh * WW;

    const uint32_t wring = sb + RING_OFF + (uint32_t)warp * WRING_BYTES;
    const uint32_t wmbar = sb + MBAR_OFF + (uint32_t)warp * (NSTAGE * 8);
    const int      yrow  = l * COUT + cg * 16;
    const int      xbase = kh * KHALF * 32;      // f offset of this warp's k-half

    // ---- init mbarriers ----
    if (tid < NWARP * NSTAGE)
        mbar_init(sb + MBAR_OFF + (uint32_t)tid * 8, 1);
    __syncthreads();

    // ---- prologue: issue chunks 0..2 of this warp's half ----
    if (elect1()) {
        #pragma unroll
        for (int k = 0; k < DIST; k++) {
            mbar_expect_tx(wmbar + (uint32_t)k * 8, WSTAGE_BYTES);
            tma_2d(wring + (uint32_t)k * WSTAGE_BYTES, &wmap, xbase + k * 32, yrow,
                   wmbar + (uint32_t)k * 8);
        }
    }

    // ---- stage patches (16 batches): front-loaded LDGs for MLP ----
    {
        const int pos = tid & 15;                 // cin group: cin = pos*4 + q
        float4   v[9];
        uint32_t adr[9];
        #pragma unroll
        for (int i = 0; i < 9; i++) {
            int s  = (tid >> 4) + i * 16;         // 0..143
            int b  = s / 9;
            int rr = s - b * 9;                   // ki*3 + kj
            int ki = rr / 3, kj = rr - ki * 3;
            int h  = oh + ki - 1;
            int wq = ow + kj - 1;
            bool ok = ((unsigned)h < HH) & ((unsigned)wq < WW);
            v[i] = make_float4(0.f, 0.f, 0.f, 0.f);
            if (ok)
                v[i] = *(const float4*)(g_xt + ((size_t)(half * NB + b) * LL + h * WW + wq) * CIN
                                        + pos * 4);
            adr[i] = sb + (uint32_t)b * PROW_BYTES + (uint32_t)(36 * pos + rr) * 4;
        }
        #pragma unroll
        for (int i = 0; i < 9; i++) {
            sts32(adr[i],       cvt_tf32(v[i].x));
            sts32(adr[i] + 36,  cvt_tf32(v[i].y));
            sts32(adr[i] + 72,  cvt_tf32(v[i].z));
            sts32(adr[i] + 108, cvt_tf32(v[i].w));
        }
    }

    // ---- fragment addressing ----
    const uint32_t a_base = sb + (uint32_t)(lane & 15) * PROW_BYTES
                          + ((lane & 16) ? 16u : 0u);
    // B = weights: [16c][32f] SW128 tile; ldsm_x4 -> 2 n-tiles (validated in R11)
    const uint32_t b_off = (uint32_t)((lane & 7) + ((lane & 16) ? 8 : 0)) * 128
                         + ((lane & 8) ? 16u : 0u);     // + ks*32, pre-swz

    float acc[2][4];
    #pragma unroll
    for (int nt = 0; nt < 2; nt++)
        #pragma unroll
        for (int q = 0; q < 4; q++) acc[nt][q] = 0.0f;

    __syncthreads();   // patch tile ready

    // ---- main loop: 9 chunks of this warp's k-half; no CTA barriers ----
    for (int k = 0; k < KHALF; k++) {
        const int kg = kh * KHALF + k;     // global chunk (A column block)

        // preload patch A-frags
        uint32_t a[4][4];
        #pragma unroll
        for (int ks = 0; ks < 4; ks++)
            ldsm_x4(a_base + (uint32_t)(kg * 128 + ks * 32),
                    a[ks][0], a[ks][1], a[ks][2], a[ks][3]);

        // issue chunk k+3 into slot (k+3)&3 (consumed at k-1)
        if (k + DIST < KHALF && elect1()) {
            const int kn   = k + DIST;
            const int slot2 = kn & (NSTAGE - 1);
            mbar_expect_tx(wmbar + (uint32_t)slot2 * 8, WSTAGE_BYTES);
            tma_2d(wring + (uint32_t)slot2 * WSTAGE_BYTES, &wmap, xbase + kn * 32, yrow,
                   wmbar + (uint32_t)slot2 * 8);
        }

        // wait for chunk k (slot k&3, parity (k>>2)&1)
        const int slot = k & (NSTAGE - 1);
        mbar_wait(wmbar + (uint32_t)slot * 8, (uint32_t)((k >> 2) & 1));

        const uint32_t wt = wring + (uint32_t)slot * WSTAGE_BYTES;
        #pragma unroll
        for (int ks = 0; ks < 4; ks++) {
            uint32_t bf[4];
            ldsm_x4(wt + swz(b_off + (uint32_t)ks * 32), bf[0], bf[1], bf[2], bf[3]);
            #pragma unroll
            for (int q = 0; q < 4; q++) bf[q] = tf32r(bf[q]);
            mma_tf32(acc[0], a[ks], bf);        // channels cg*16 + 0..7
            mma_tf32(acc[1], a[ks], bf + 2);    // channels cg*16 + 8..15
        }
    }

    // ---- cross-warp k-reduction (reuse patch smem) + epilogue ----
    // D m16n8 layout: d0=(g,2t) d1=(g,2t+1) d2=(g+8,2t) d3=(g+8,2t+1)
    const int g  = lane >> 2;
    const int t2 = (lane & 3) * 2;

    __syncthreads();   // all patch reads done; safe to reuse as reduction area
    float* red = (float*)smem;        // [4 cg][16 b][16 c] = 4 KB

    if (kh == 1) {
        float* rb = red + cg * 256;
        #pragma unroll
        for (int nt = 0; nt < 2; nt++) {
            const int c = nt * 8 + t2;
            rb[(g    ) * 16 + c    ] = acc[nt][0];
            rb[(g    ) * 16 + c + 1] = acc[nt][1];
            rb[(g + 8) * 16 + c    ] = acc[nt][2];
            rb[(g + 8) * 16 + c + 1] = acc[nt][3];
        }
    }
    __syncthreads();

    if (kh == 0) {
        const float* rb = red + cg * 256;
        const float* bl = bias + (size_t)l * COUT;
        #pragma unroll
        for (int nt = 0; nt < 2; nt++) {
            const int cl = nt * 8 + t2;
            const int c  = cg * 16 + cl;
            const float bv0 = bl[c];
            const float bv1 = bl[c + 1];
            const int b0 = half * NB + g;
            out[((size_t)((b0    ) * COUT) + c    ) * LL + l] = acc[nt][0] + rb[(g    ) * 16 + cl    ] + bv0;
            out[((size_t)((b0    ) * COUT) + c + 1) * LL + l] = acc[nt][1] + rb[(g    ) * 16 + cl + 1] + bv1;
            out[((size_t)((b0 + 8) * COUT) + c    ) * LL + l] = acc[nt][2] + rb[(g + 8) * 16 + cl    ] + bv0;
            out[((size_t)((b0 + 8) * COUT) + c + 1) * LL + l] = acc[nt][3] + rb[(g + 8) * 16 + cl + 1] + bv1;
        }
    }
}

// ---------------- host ----------------
typedef CUresult (*EncodeTiledFn)(
    CUtensorMap*, CUtensorMapDataType, cuuint32_t, void*,
    const cuuint64_t*, const cuuint64_t*, const cuuint32_t*, const cuuint32_t*,
    CUtensorMapInterleave, CUtensorMapSwizzle, CUtensorMapL2promotion,
    CUtensorMapFloatOOBfill);

extern "C" void kernel_launch(void* const* d_in, const int* in_sizes, int n_in,
                              void* d_out, int out_size)
{
    const float* x    = (const float*)d_in[0];   // [32,64,56,56]
    const float* w    = (const float*)d_in[1];   // [3136,64,576]
    const float* bias = (const float*)d_in[2];   // [3136,64]
    float* out        = (float*)d_out;           // [32,64,56,56]

    // weight tensor map: 2D [576 f][200704 rows = c + 64*l], box [32, 16], SW128
    void* fp = nullptr;
    cudaDriverEntryPointQueryResult qr;
    cudaGetDriverEntryPointByVersion("cuTensorMapEncodeTiled", &fp, 12000,
                                     cudaEnableDefault, &qr);
    EncodeTiledFn encode = (EncodeTiledFn)fp;

    CUtensorMap wmap;
    cuuint64_t dims[2]    = {(cuuint64_t)FEAT, (cuuint64_t)LL * COUT};
    cuuint64_t strides[1] = {(cuuint64_t)FEAT * sizeof(float)};
    cuuint32_t box[2]     = {32, 16};
    cuuint32_t estr[2]    = {1, 1};
    encode(&wmap, CU_TENSOR_MAP_DATA_TYPE_FLOAT32, 2, (void*)w,
           dims, strides, box, estr,
           CU_TENSOR_MAP_INTERLEAVE_NONE, CU_TENSOR_MAP_SWIZZLE_128B,
           CU_TENSOR_MAP_L2_PROMOTION_L2_128B, CU_TENSOR_MAP_FLOAT_OOB_FILL_NONE);

    transpose_x<<<dim3(LL / 32, CIN / 32, BATCH), 256>>>(x);

    cudaFuncSetAttribute(lc2d_mma, cudaFuncAttributeMaxDynamicSharedMemorySize, SMEM_TOTAL);
    lc2d_mma<<<LL * 2, NTHREADS, SMEM_TOTAL>>>(wmap, bias, out);
}

// round 14
// speedup vs baseline: 2.1578x; 1.1661x over previous
#include <cuda_runtime.h>
#include <cuda.h>
#include <cstdint>

#define BATCH   32
#define CIN     64
#define COUT    64
#define HH      56
#define WW      56
#define LL      3136
#define FEAT    576
#define NCHUNK  18            // 576 / 32 f
#define KHALF   9             // chunks per k-half
#define NTHREADS 256          // 8 warps = 4 channel-groups x 2 k-halves
#define NWARP   8
#define NSTAGE  4
#define DIST    3

// ---- smem ----
#define PROW_BYTES  2320
#define NB          16
#define PATCH_BYTES (NB * PROW_BYTES)       // 37120
#define RING_OFF     37888                  // 1024-aligned
#define WSTAGE_BYTES 2048
#define WRING_BYTES  (NSTAGE * WSTAGE_BYTES)            // 8192
#define MBAR_OFF     (RING_OFF + NWARP * WRING_BYTES)   // 103424
#define SMEM_TOTAL   (MBAR_OFF + NWARP * NSTAGE * 8)    // 103680

__device__ float g_xt[(size_t)BATCH * LL * CIN];
__device__ float g_out_s[(size_t)LL * BATCH * COUT];    // [l][b][c]

// ---------------- helpers ----------------
__device__ __forceinline__ uint32_t swz(uint32_t o) { return o ^ ((o >> 3) & 0x70); }

__device__ __forceinline__ uint32_t cvt_tf32(float v) {
    uint32_t t;
    asm("cvt.rna.tf32.f32 %0, %1;" : "=r"(t) : "f"(v));
    return t;
}
__device__ __forceinline__ uint32_t tf32r(uint32_t bits) {
    uint32_t t;
    asm("cvt.rna.tf32.f32 %0, %1;" : "=r"(t) : "f"(__uint_as_float(bits)));
    return t;
}

__device__ __forceinline__ void sts32(uint32_t a, uint32_t v) {
    asm volatile("st.shared.b32 [%0], %1;" :: "r"(a), "r"(v) : "memory");
}

__device__ __forceinline__ void ldsm_x4(uint32_t addr, uint32_t& r0, uint32_t& r1,
                                        uint32_t& r2, uint32_t& r3) {
    asm volatile("ldmatrix.sync.aligned.m8n8.x4.shared.b16 {%0,%1,%2,%3}, [%4];"
                 : "=r"(r0), "=r"(r1), "=r"(r2), "=r"(r3) : "r"(addr));
}

__device__ __forceinline__ void mma_tf32(float* d, const uint32_t* a, const uint32_t* b) {
    asm volatile("mma.sync.aligned.m16n8k8.row.col.f32.tf32.tf32.f32 "
                 "{%0,%1,%2,%3}, {%4,%5,%6,%7}, {%8,%9}, {%0,%1,%2,%3};"
                 : "+f"(d[0]), "+f"(d[1]), "+f"(d[2]), "+f"(d[3])
                 : "r"(a[0]), "r"(a[1]), "r"(a[2]), "r"(a[3]),
                   "r"(b[0]), "r"(b[1]));
}

__device__ __forceinline__ uint32_t elect1() {
    uint32_t p;
    asm volatile("{\n\t.reg .pred p;\n\telect.sync _|p, 0xFFFFFFFF;\n\tselp.b32 %0, 1, 0, p;\n\t}"
                 : "=r"(p));
    return p;
}

__device__ __forceinline__ void mbar_init(uint32_t mbar, uint32_t cnt) {
    asm volatile("mbarrier.init.shared.b64 [%0], %1;" :: "r"(mbar), "r"(cnt) : "memory");
}
__device__ __forceinline__ void mbar_expect_tx(uint32_t mbar, uint32_t bytes) {
    asm volatile("mbarrier.arrive.expect_tx.shared.b64 _, [%0], %1;"
                 :: "r"(mbar), "r"(bytes) : "memory");
}
__device__ __forceinline__ void mbar_wait(uint32_t mbar, uint32_t parity) {
    asm volatile("{\n\t.reg .pred P;\n\t"
                 "WL_%=:\n\t"
                 "mbarrier.try_wait.parity.acquire.cta.shared::cta.b64 P, [%0], %1, 0x989680;\n\t"
                 "@P bra.uni WD_%=;\n\t"
                 "bra.uni WL_%=;\n\t"
                 "WD_%=:\n\t}"
                 :: "r"(mbar), "r"(parity) : "memory");
}

__device__ __forceinline__ void tma_2d(uint32_t smem_dst, const void* tmap,
                                       int x, int y, uint32_t mbar) {
    asm volatile("cp.async.bulk.tensor.2d.shared::cta.global.tile.mbarrier::complete_tx::bytes "
                 "[%0], [%1, {%2, %3}], [%4];"
                 :: "r"(smem_dst), "l"(tmap), "r"(x), "r"(y), "r"(mbar) : "memory");
}

// ---------------- kernel 1: x NCHW -> NHWC transpose ----------------
__global__ void __launch_bounds__(256) transpose_x(const float* __restrict__ x) {
    __shared__ float tile[32][33];
    const int b  = blockIdx.z;
    const int c0 = blockIdx.y * 32;
    const int s0 = blockIdx.x * 32;
    const int tx = threadIdx.x & 31;
    const int ty = threadIdx.x >> 5;
    #pragma unroll
    for (int i = 0; i < 4; i++)
        tile[ty + 8 * i][tx] = x[((size_t)b * CIN + c0 + ty + 8 * i) * LL + s0 + tx];
    __syncthreads();
    #pragma unroll
    for (int i = 0; i < 4; i++)
        g_xt[((size_t)b * LL + s0 + ty + 8 * i) * CIN + c0 + tx] = tile[tx][ty + 8 * i];
}

// ---------------- kernel 3: scratch [l][b*64+c] -> out [b*64+c][l] ----------------
__global__ void __launch_bounds__(256) transpose_out(float* __restrict__ out) {
    __shared__ float tile[32][33];
    const int l0 = blockIdx.x * 32;
    const int m0 = blockIdx.y * 32;        // m = b*64 + c
    const int tx = threadIdx.x & 31;
    const int ty = threadIdx.x >> 5;
    #pragma unroll
    for (int i = 0; i < 4; i++)
        tile[ty + 8 * i][tx] = g_out_s[(size_t)(l0 + ty + 8 * i) * (BATCH * COUT) + m0 + tx];
    __syncthreads();
    #pragma unroll
    for (int i = 0; i < 4; i++)
        out[(size_t)(m0 + ty + 8 * i) * LL + l0 + tx] = tile[tx][ty + 8 * i];
}

// ---------------- kernel 2: per-(location, batch-half) GEMM, k-split warps ----------------
__global__ void __launch_bounds__(NTHREADS, 2)
lc2d_mma(const __grid_constant__ CUtensorMap wmap,
         const float* __restrict__ bias)
{
    extern __shared__ __align__(1024) char smem[];
    const uint32_t sb = (uint32_t)__cvta_generic_to_shared(smem);

    const int tid  = threadIdx.x;
    const int lane = tid & 31;
    const int warp = tid >> 5;
    const int kh   = warp & 1;        // k half: chunks [9*kh, 9*kh+9)
    const int cg   = warp >> 1;       // channel group: channels [16*cg, 16*cg+16)
    const int l    = blockIdx.x >> 1;
    const int half = blockIdx.x & 1;  // batches [16*half, 16*half+16)
    const int oh   = l / WW;
    const int ow   = l - oh * WW;

    const uint32_t wring = sb + RING_OFF + (uint32_t)warp * WRING_BYTES;
    const uint32_t wmbar = sb + MBAR_OFF + (uint32_t)warp * (NSTAGE * 8);
    const int      yrow  = l * COUT + cg * 16;
    const int      xbase = kh * KHALF * 32;      // f offset of this warp's k-half

    // ---- init mbarriers ----
    if (tid < NWARP * NSTAGE)
        mbar_init(sb + MBAR_OFF + (uint32_t)tid * 8, 1);
    __syncthreads();

    // ---- prologue: issue chunks 0..2 of this warp's half ----
    if (elect1()) {
        #pragma unroll
        for (int k = 0; k < DIST; k++) {
            mbar_expect_tx(wmbar + (uint32_t)k * 8, WSTAGE_BYTES);
            tma_2d(wring + (uint32_t)k * WSTAGE_BYTES, &wmap, xbase + k * 32, yrow,
                   wmbar + (uint32_t)k * 8);
        }
    }

    // ---- stage patches (16 batches): front-loaded LDGs for MLP ----
    {
        const int pos = tid & 15;                 // cin group: cin = pos*4 + q
        float4   v[9];
        uint32_t adr[9];
        #pragma unroll
        for (int i = 0; i < 9; i++) {
            int s  = (tid >> 4) + i * 16;         // 0..143
            int b  = s / 9;
            int rr = s - b * 9;                   // ki*3 + kj
            int ki = rr / 3, kj = rr - ki * 3;
            int h  = oh + ki - 1;
            int wq = ow + kj - 1;
            bool ok = ((unsigned)h < HH) & ((unsigned)wq < WW);
            v[i] = make_float4(0.f, 0.f, 0.f, 0.f);
            if (ok)
                v[i] = *(const float4*)(g_xt + ((size_t)(half * NB + b) * LL + h * WW + wq) * CIN
                                        + pos * 4);
            adr[i] = sb + (uint32_t)b * PROW_BYTES + (uint32_t)(36 * pos + rr) * 4;
        }
        #pragma unroll
        for (int i = 0; i < 9; i++) {
            sts32(adr[i],       cvt_tf32(v[i].x));
            sts32(adr[i] + 36,  cvt_tf32(v[i].y));
            sts32(adr[i] + 72,  cvt_tf32(v[i].z));
            sts32(adr[i] + 108, cvt_tf32(v[i].w));
        }
    }

    // ---- fragment addressing ----
    const uint32_t a_base = sb + (uint32_t)(lane & 15) * PROW_BYTES
                          + ((lane & 16) ? 16u : 0u);
    // B = weights: [16c][32f] SW128 tile; ldsm_x4 -> 2 n-tiles
    // swz(b_off + ks*32) hoisted: stage bases are 2KB-aligned, swizzle bits < 1KB
    uint32_t b_swz[4];
    {
        const uint32_t b_off = (uint32_t)((lane & 7) + ((lane & 16) ? 8 : 0)) * 128
                             + ((lane & 8) ? 16u : 0u);
        #pragma unroll
        for (int ks = 0; ks < 4; ks++)
            b_swz[ks] = swz(b_off + (uint32_t)ks * 32);
    }

    float acc[2][4];
    #pragma unroll
    for (int nt = 0; nt < 2; nt++)
        #pragma unroll
        for (int q = 0; q < 4; q++) acc[nt][q] = 0.0f;

    __syncthreads();   // patch tile ready

    // ---- main loop: 9 chunks of this warp's k-half; no CTA barriers ----
    for (int k = 0; k < KHALF; k++) {
        const int kg = kh * KHALF + k;     // global chunk (A column block)

        // preload patch A-frags
        uint32_t a[4][4];
        #pragma unroll
        for (int ks = 0; ks < 4; ks++)
            ldsm_x4(a_base + (uint32_t)(kg * 128 + ks * 32),
                    a[ks][0], a[ks][1], a[ks][2], a[ks][3]);

        // issue chunk k+3 into slot (k+3)&3 (consumed at k-1)
        if (k + DIST < KHALF && elect1()) {
            const int kn    = k + DIST;
            const int slot2 = kn & (NSTAGE - 1);
            mbar_expect_tx(wmbar + (uint32_t)slot2 * 8, WSTAGE_BYTES);
            tma_2d(wring + (uint32_t)slot2 * WSTAGE_BYTES, &wmap, xbase + kn * 32, yrow,
                   wmbar + (uint32_t)slot2 * 8);
        }

        // wait for chunk k (slot k&3, parity (k>>2)&1)
        const int slot = k & (NSTAGE - 1);
        mbar_wait(wmbar + (uint32_t)slot * 8, (uint32_t)((k >> 2) & 1));

        const uint32_t wt = wring + (uint32_t)slot * WSTAGE_BYTES;
        #pragma unroll
        for (int ks = 0; ks < 4; ks++) {
            uint32_t bf[4];
            ldsm_x4(wt + b_swz[ks], bf[0], bf[1], bf[2], bf[3]);
            #pragma unroll
            for (int q = 0; q < 4; q++) bf[q] = tf32r(bf[q]);
            mma_tf32(acc[0], a[ks], bf);        // channels cg*16 + 0..7
            mma_tf32(acc[1], a[ks], bf + 2);    // channels cg*16 + 8..15
        }
    }

    // ---- cross-warp k-reduction (reuse patch smem) + coalesced epilogue ----
    // D m16n8 layout: d0=(g,2t) d1=(g,2t+1) d2=(g+8,2t) d3=(g+8,2t+1)
    const int g  = lane >> 2;
    const int t2 = (lane & 3) * 2;

    __syncthreads();   // all patch reads done; safe to reuse as reduction area
    float* red = (float*)smem;        // [4 cg][16 b][16 c] = 4 KB

    if (kh == 1) {
        float* rb = red + cg * 256;
        #pragma unroll
        for (int nt = 0; nt < 2; nt++) {
            const int c = nt * 8 + t2;
            rb[(g    ) * 16 + c    ] = acc[nt][0];
            rb[(g    ) * 16 + c + 1] = acc[nt][1];
            rb[(g + 8) * 16 + c    ] = acc[nt][2];
            rb[(g + 8) * 16 + c + 1] = acc[nt][3];
        }
    }
    __syncthreads();

    if (kh == 0) {
        const float* rb = red + cg * 256;
        const float* bl = bias + (size_t)l * COUT;
        float* os = g_out_s + (size_t)l * (BATCH * COUT) + (half * NB) * COUT;
        #pragma unroll
        for (int nt = 0; nt < 2; nt++) {
            const int cl = nt * 8 + t2;
            const int c  = cg * 16 + cl;
            const float bv0 = bl[c];
            const float bv1 = bl[c + 1];
            float2 v0, v1;
            v0.x = acc[nt][0] + rb[(g    ) * 16 + cl    ] + bv0;
            v0.y = acc[nt][1] + rb[(g    ) * 16 + cl + 1] + bv1;
            v1.x = acc[nt][2] + rb[(g + 8) * 16 + cl    ] + bv0;
            v1.y = acc[nt][3] + rb[(g + 8) * 16 + cl + 1] + bv1;
            *(float2*)(os + (size_t)(g    ) * COUT + c) = v0;
            *(float2*)(os + (size_t)(g + 8) * COUT + c) = v1;
        }
    }
}

// ---------------- host ----------------
typedef CUresult (*EncodeTiledFn)(
    CUtensorMap*, CUtensorMapDataType, cuuint32_t, void*,
    const cuuint64_t*, const cuuint64_t*, const cuuint32_t*, const cuuint32_t*,
    CUtensorMapInterleave, CUtensorMapSwizzle, CUtensorMapL2promotion,
    CUtensorMapFloatOOBfill);

extern "C" void kernel_launch(void* const* d_in, const int* in_sizes, int n_in,
                              void* d_out, int out_size)
{
    const float* x    = (const float*)d_in[0];   // [32,64,56,56]
    const float* w    = (const float*)d_in[1];   // [3136,64,576]
    const float* bias = (const float*)d_in[2];   // [3136,64]
    float* out        = (float*)d_out;           // [32,64,56,56]

    // weight tensor map: 2D [576 f][200704 rows = c + 64*l], box [32, 16], SW128
    void* fp = nullptr;
    cudaDriverEntryPointQueryResult qr;
    cudaGetDriverEntryPointByVersion("cuTensorMapEncodeTiled", &fp, 12000,
                                     cudaEnableDefault, &qr);
    EncodeTiledFn encode = (EncodeTiledFn)fp;

    CUtensorMap wmap;
    cuuint64_t dims[2]    = {(cuuint64_t)FEAT, (cuuint64_t)LL * COUT};
    cuuint64_t strides[1] = {(cuuint64_t)FEAT * sizeof(float)};
    cuuint32_t box[2]     = {32, 16};
    cuuint32_t estr[2]    = {1, 1};
    encode(&wmap, CU_TENSOR_MAP_DATA_TYPE_FLOAT32, 2, (void*)w,
           dims, strides, box, estr,
           CU_TENSOR_MAP_INTERLEAVE_NONE, CU_TENSOR_MAP_SWIZZLE_128B,
           CU_TENSOR_MAP_L2_PROMOTION_L2_128B, CU_TENSOR_MAP_FLOAT_OOB_FILL_NONE);

    transpose_x<<<dim3(LL / 32, CIN / 32, BATCH), 256>>>(x);

    cudaFuncSetAttribute(lc2d_mma, cudaFuncAttributeMaxDynamicSharedMemorySize, SMEM_TOTAL);
    lc2d_mma<<<LL * 2, NTHREADS, SMEM_TOTAL>>>(wmap, bias);

    transpose_out<<<dim3(LL / 32, (BATCH * COUT) / 32), 256>>>(out);
}